// round 1
// baseline (speedup 1.0000x reference)
#include <cuda_runtime.h>
#include <math.h>

// ---------------- problem constants ----------------
#define BB 2
#define LL 1024
#define HH 768
#define DI 1536
#define NN 16
#define KC 4          // conv kernel width
#define RR 48
#define TOK (BB*LL)   // 2048 tokens
#define N1 (2*DI*4)   // 12288
#define N2 (2*DI)     // 3072
#define N3 (4*DI)     // 6144

// ---------------- device scratch (no allocs allowed) ----------------
__device__ float g_t1  [(size_t)TOK * N1];   // up-proj act, reused for t2 later
__device__ float g_P   [(size_t)TOK * N2];   // proj: cols [0,DI)=hs, [DI,2DI)=gate
__device__ float g_hsc [(size_t)TOK * DI];   // conv+silu output, token-major
__device__ float g_ssmp[(size_t)TOK * 80];   // x_proj output (R + 2N = 80)
__device__ float g_dt  [(size_t)TOK * DI];   // softplus(dt), token-major
__device__ float g_z   [(size_t)TOK * DI];   // scan output * gate, token-major
__device__ float g_dtwT[RR * DI];            // dt_w transposed [R][DI]
__device__ float g_xwT [DI * 80];            // x_proj_w transposed [DI][80]

__device__ __forceinline__ float silu_f(float x) {
    return x / (1.f + __expf(-x));
}

// ---------------------------------------------------------------
// SGEMM NT: C[M,N] = A[M,K] (row-major) * B[N,K] (row-major) ^T
// BM=BN=128, BK=8, 256 threads, 8x8 per thread (4+4 split),
// double-buffered shared memory.
// Requires M%128==0, N%128==0, K%8==0, K%4==0 for float4 loads.
// ---------------------------------------------------------------
template<bool SILU>
__global__ __launch_bounds__(256)
void sgemm_nt(const float* __restrict__ A, const float* __restrict__ B,
              float* __restrict__ C, int M, int N, int K)
{
    __shared__ float As[2][8][128];
    __shared__ float Bs[2][8][128];

    const int tid  = threadIdx.x;
    const int bm   = blockIdx.y * 128;
    const int bn   = blockIdx.x * 128;
    const int lrow = tid >> 1;            // 0..127
    const int lcol = (tid & 1) << 2;      // 0 or 4
    const float* Ag = A + (size_t)(bm + lrow) * K + lcol;
    const float* Bg = B + (size_t)(bn + lrow) * K + lcol;
    const int tx = tid & 15;
    const int ty = tid >> 4;

    float acc[8][8];
    #pragma unroll
    for (int i = 0; i < 8; i++)
        #pragma unroll
        for (int j = 0; j < 8; j++) acc[i][j] = 0.f;

    // prologue: stage 0
    {
        float4 a4 = *(const float4*)Ag;
        float4 b4 = *(const float4*)Bg;
        As[0][lcol+0][lrow] = a4.x; As[0][lcol+1][lrow] = a4.y;
        As[0][lcol+2][lrow] = a4.z; As[0][lcol+3][lrow] = a4.w;
        Bs[0][lcol+0][lrow] = b4.x; Bs[0][lcol+1][lrow] = b4.y;
        Bs[0][lcol+2][lrow] = b4.z; Bs[0][lcol+3][lrow] = b4.w;
    }
    __syncthreads();

    const int nk = K >> 3;
    for (int kt = 0; kt < nk; kt++) {
        const int cur = kt & 1;
        const bool has = (kt + 1 < nk);
        float4 a4n, b4n;
        if (has) {
            a4n = *(const float4*)(Ag + ((size_t)(kt + 1) << 3));
            b4n = *(const float4*)(Bg + ((size_t)(kt + 1) << 3));
        }
        #pragma unroll
        for (int kk = 0; kk < 8; kk++) {
            float4 a0 = *(const float4*)&As[cur][kk][(ty << 2)];
            float4 a1 = *(const float4*)&As[cur][kk][64 + (ty << 2)];
            float4 b0 = *(const float4*)&Bs[cur][kk][(tx << 2)];
            float4 b1 = *(const float4*)&Bs[cur][kk][64 + (tx << 2)];
            float a[8] = {a0.x, a0.y, a0.z, a0.w, a1.x, a1.y, a1.z, a1.w};
            float b[8] = {b0.x, b0.y, b0.z, b0.w, b1.x, b1.y, b1.z, b1.w};
            #pragma unroll
            for (int i = 0; i < 8; i++)
                #pragma unroll
                for (int j = 0; j < 8; j++)
                    acc[i][j] = fmaf(a[i], b[j], acc[i][j]);
        }
        if (has) {
            const int nxt = cur ^ 1;
            As[nxt][lcol+0][lrow] = a4n.x; As[nxt][lcol+1][lrow] = a4n.y;
            As[nxt][lcol+2][lrow] = a4n.z; As[nxt][lcol+3][lrow] = a4n.w;
            Bs[nxt][lcol+0][lrow] = b4n.x; Bs[nxt][lcol+1][lrow] = b4n.y;
            Bs[nxt][lcol+2][lrow] = b4n.z; Bs[nxt][lcol+3][lrow] = b4n.w;
        }
        __syncthreads();
    }

    // epilogue
    #pragma unroll
    for (int i = 0; i < 8; i++) {
        const int r = bm + ((i < 4) ? ((ty << 2) + i) : (64 + (ty << 2) + i - 4));
        float v[8];
        #pragma unroll
        for (int j = 0; j < 8; j++) {
            v[j] = acc[i][j];
            if (SILU) v[j] = silu_f(v[j]);
        }
        float4 v0 = make_float4(v[0], v[1], v[2], v[3]);
        float4 v1 = make_float4(v[4], v[5], v[6], v[7]);
        *(float4*)&C[(size_t)r * N + bn + (tx << 2)]      = v0;
        *(float4*)&C[(size_t)r * N + bn + 64 + (tx << 2)] = v1;
    }
}

// ---------------------------------------------------------------
// small-weight transpose: dst[c*rows + r] = src[r*cols + c]
// ---------------------------------------------------------------
__global__ void transpose_small(const float* __restrict__ src, float* __restrict__ dst,
                                int rows, int cols)
{
    int i = blockIdx.x * blockDim.x + threadIdx.x;
    if (i < rows * cols) {
        int r = i / cols, c = i % cols;
        dst[(size_t)c * rows + r] = src[i];
    }
}

// ---------------------------------------------------------------
// depthwise causal conv (K=4) + bias + SiLU.
// reads hs channel-slice of P (cols [0,DI)), writes token-major hsc.
// ---------------------------------------------------------------
__global__ void conv_silu_kernel(const float* __restrict__ conv_w,
                                 const float* __restrict__ conv_b)
{
    int idx = blockIdx.x * blockDim.x + threadIdx.x;  // over TOK*DI
    if (idx >= TOK * DI) return;
    int d = idx % DI;
    int t = idx / DI;
    int l = t % LL;
    int b = t / LL;

    float4 w = *(const float4*)&conv_w[d * KC];   // conv_w[d,0,0..3]
    float acc = conv_b[d];
    const float* Pb = g_P + (size_t)b * LL * N2 + d;
    float wj[4] = {w.x, w.y, w.z, w.w};
    #pragma unroll
    for (int j = 0; j < KC; j++) {
        int ls = l - (KC - 1) + j;
        if (ls >= 0) acc = fmaf(wj[j], Pb[(size_t)ls * N2], acc);
    }
    g_hsc[idx] = silu_f(acc);
}

// ---------------------------------------------------------------
// x_proj: ssmp[t,k] = sum_d hsc[t,d] * xwT[d,k],  k in [0,80)
// one block per token, 96 threads (80 active).
// ---------------------------------------------------------------
__global__ void xproj_kernel()
{
    __shared__ float sh[DI];
    const int t = blockIdx.x;
    for (int i = threadIdx.x; i < DI; i += blockDim.x)
        sh[i] = g_hsc[(size_t)t * DI + i];
    __syncthreads();
    const int k = threadIdx.x;
    if (k < 80) {
        float acc = 0.f;
        #pragma unroll 8
        for (int d = 0; d < DI; d++)
            acc = fmaf(sh[d], g_xwT[d * 80 + k], acc);
        g_ssmp[(size_t)t * 80 + k] = acc;
    }
}

// ---------------------------------------------------------------
// dt: dt[t,d] = softplus( ts[t,:] @ dt_w[d,:] + dt_b[d] )
// one block per token, 256 threads.
// ---------------------------------------------------------------
__global__ void dt_kernel(const float* __restrict__ dt_b)
{
    __shared__ float ts[RR];
    const int t = blockIdx.x;
    if (threadIdx.x < RR) ts[threadIdx.x] = g_ssmp[(size_t)t * 80 + threadIdx.x];
    __syncthreads();
    for (int d = threadIdx.x; d < DI; d += blockDim.x) {
        float acc = dt_b[d];
        #pragma unroll
        for (int r = 0; r < RR; r++)
            acc = fmaf(ts[r], g_dtwT[r * DI + d], acc);
        float sp = (acc > 20.f) ? acc : log1pf(expf(acc));
        g_dt[(size_t)t * DI + d] = sp;
    }
}

// ---------------------------------------------------------------
// selective scan. thread per (b,d), 16-state in registers.
// z[t,d] = (y + u*D[d]) * silu(gate)
// ---------------------------------------------------------------
__global__ void scan_kernel(const float* __restrict__ A_log,
                            const float* __restrict__ Dp)
{
    const int d = blockIdx.x * blockDim.x + threadIdx.x;  // 0..DI-1
    const int b = blockIdx.y;
    if (d >= DI) return;

    float Arow[NN];
    #pragma unroll
    for (int n = 0; n < NN; n++) Arow[n] = -expf(A_log[d * NN + n]);
    const float Dd = Dp[d];

    float s[NN];
    #pragma unroll
    for (int n = 0; n < NN; n++) s[n] = 0.f;

    for (int l = 0; l < LL; l++) {
        const size_t t = (size_t)b * LL + l;
        const float dtv = g_dt[t * DI + d];
        const float u   = g_hsc[t * DI + d];
        const float gte = g_P[t * N2 + DI + d];
        const float* bc = g_ssmp + t * 80 + RR;   // B then C, 16 each
        const float dtu = dtv * u;
        float y = 0.f;
        #pragma unroll
        for (int n = 0; n < NN; n++) {
            const float Bn = __ldg(bc + n);
            const float Cn = __ldg(bc + NN + n);
            const float dA = __expf(dtv * Arow[n]);
            s[n] = fmaf(dA, s[n], dtu * Bn);
            y = fmaf(s[n], Cn, y);
        }
        float zz = fmaf(u, Dd, y);
        zz *= silu_f(gte);
        g_z[t * DI + d] = zz;
    }
}

// ---------------------------------------------------------------
extern "C" void kernel_launch(void* const* d_in, const int* in_sizes, int n_in,
                              void* d_out, int out_size)
{
    const float* x          = (const float*)d_in[0];
    const float* in_up_w    = (const float*)d_in[1];
    const float* in_down_w  = (const float*)d_in[2];
    const float* conv_w     = (const float*)d_in[3];
    const float* conv_b     = (const float*)d_in[4];
    const float* x_proj_w   = (const float*)d_in[5];
    const float* dt_w       = (const float*)d_in[6];
    const float* dt_b       = (const float*)d_in[7];
    const float* A_log      = (const float*)d_in[8];
    const float* Dp         = (const float*)d_in[9];
    const float* out_up_w   = (const float*)d_in[10];
    const float* out_down_w = (const float*)d_in[11];
    float* out = (float*)d_out;

    float *t1, *P, *z;
    cudaGetSymbolAddress((void**)&t1, g_t1);
    cudaGetSymbolAddress((void**)&P,  g_P);
    cudaGetSymbolAddress((void**)&z,  g_z);
    float *xwT, *dtwT;
    cudaGetSymbolAddress((void**)&xwT,  g_xwT);
    cudaGetSymbolAddress((void**)&dtwT, g_dtwT);

    // 1) up-proj + SiLU : [TOK,HH] x [N1,HH]^T -> [TOK,N1]
    sgemm_nt<true ><<<dim3(N1/128, TOK/128), 256>>>(x, in_up_w, t1, TOK, N1, HH);
    // 2) down-proj : [TOK,N1] x [N2,N1]^T -> [TOK,N2]  (hs | gate)
    sgemm_nt<false><<<dim3(N2/128, TOK/128), 256>>>(t1, in_down_w, P, TOK, N2, N1);
    // 3) depthwise causal conv + SiLU -> hsc (token-major)
    conv_silu_kernel<<<(TOK*DI + 255)/256, 256>>>(conv_w, conv_b);
    // 4) transpose small weights for coalesced reads
    transpose_small<<<(80*DI + 255)/256, 256>>>(x_proj_w, xwT, 80, DI);
    transpose_small<<<(DI*RR + 255)/256, 256>>>(dt_w, dtwT, DI, RR);
    // 5) x_proj -> [TOK,80]
    xproj_kernel<<<TOK, 96>>>();
    // 6) dt = softplus(ts @ dt_w^T + dt_b)
    dt_kernel<<<TOK, 256>>>(dt_b);
    // 7) selective scan + D skip + gate -> z (token-major)
    scan_kernel<<<dim3(DI/128, BB), 128>>>(A_log, Dp);
    // 8) out up-proj + SiLU : [TOK,DI] x [N3,DI]^T -> [TOK,N3]  (reuse t1)
    sgemm_nt<true ><<<dim3(N3/128, TOK/128), 256>>>(z, out_up_w, t1, TOK, N3, DI);
    // 9) out down-proj : [TOK,N3] x [HH,N3]^T -> [TOK,HH]
    sgemm_nt<false><<<dim3(HH/128, TOK/128), 256>>>(t1, out_down_w, out, TOK, HH, N3);
}

// round 3
// speedup vs baseline: 1.2405x; 1.2405x over previous
#include <cuda_runtime.h>
#include <math.h>
#include <stdint.h>

// ---------------- problem constants ----------------
#define BB 2
#define LL 1024
#define HH 768
#define DI 1536
#define NN 16
#define KC 4          // conv kernel width
#define RR 48
#define TOK (BB*LL)   // 2048 tokens
#define N1 (2*DI*4)   // 12288
#define N2 (2*DI)     // 3072
#define N3 (4*DI)     // 6144

// ---------------- device scratch (no allocs allowed) ----------------
__device__ float g_t1  [(size_t)TOK * N1];   // up-proj act, reused later
__device__ float g_P   [(size_t)TOK * N2];   // proj: cols [0,DI)=hs, [DI,2DI)=gate
__device__ float g_hsc [(size_t)TOK * DI];   // conv+silu output, token-major
__device__ float g_ssmp[(size_t)TOK * 80];   // x_proj output (R + 2N = 80)
__device__ float g_dt  [(size_t)TOK * DI];   // softplus(dt), token-major
__device__ float g_z   [(size_t)TOK * DI];   // scan output * gate, token-major
__device__ float g_dtwT[RR * DI];            // dt_w transposed [R][DI]
__device__ float g_xwT [DI * 80];            // x_proj_w transposed [DI][80]

__device__ __forceinline__ float silu_f(float x) {
    return x / (1.f + __expf(-x));
}

// ===================== mma.sync tf32 helpers =====================
__device__ __forceinline__ uint32_t smem_u32(const void* p) {
    uint32_t a;
    asm("{ .reg .u64 t; cvta.to.shared.u64 t, %1; cvt.u32.u64 %0, t; }"
        : "=r"(a) : "l"(p));
    return a;
}

#define CP_ASYNC16(dst, src) \
    asm volatile("cp.async.cg.shared.global [%0], [%1], 16;" \
                 :: "r"(dst), "l"(src) : "memory")
#define CP_COMMIT() asm volatile("cp.async.commit_group;" ::: "memory")
#define CP_WAIT1()  asm volatile("cp.async.wait_group 1;" ::: "memory")

__device__ __forceinline__ void split_tf32(float x, uint32_t& hi, uint32_t& lo) {
    uint32_t h;
    asm("cvt.rna.tf32.f32 %0, %1;" : "=r"(h) : "f"(x));
    hi = h;
    lo = __float_as_uint(x - __uint_as_float(h));  // HW truncates lo to tf32
}

__device__ __forceinline__ void mma_tf32(float* c, const uint32_t* a, const uint32_t* b) {
    asm volatile("mma.sync.aligned.m16n8k8.row.col.f32.tf32.tf32.f32 "
                 "{%0,%1,%2,%3}, {%4,%5,%6,%7}, {%8,%9}, {%0,%1,%2,%3};"
                 : "+f"(c[0]), "+f"(c[1]), "+f"(c[2]), "+f"(c[3])
                 : "r"(a[0]), "r"(a[1]), "r"(a[2]), "r"(a[3]),
                   "r"(b[0]), "r"(b[1]));
}

// =====================================================================
// GEMM NT via mma.sync tf32x3:
//   C[M,N] = A[M,K] (row-major) * B[N,K] (row-major)^T
// 128x128x16 tiles, 256 threads (2x4 warps, 64x32 per warp),
// 3-stage cp.async pipeline, fp32 in smem (stride 20 pad), split in regs.
// Requires M%128==0, N%128==0, K%16==0.
// =====================================================================
#define BKT 16
#define STAGES 3
#define AS_STRIDE 20                       // floats per smem row (pad 16 -> 20)
#define TILE_FLOATS (128 * AS_STRIDE)      // 2560 floats per operand tile
#define STAGE_FLOATS (2 * TILE_FLOATS)     // A + B
#define GSMEM_BYTES (STAGES * STAGE_FLOATS * 4)   // 61440

template<bool SILU>
__global__ __launch_bounds__(256)
void gemm_tf32_mma(const float* __restrict__ A, const float* __restrict__ B,
                   float* __restrict__ C, int M, int N, int K)
{
    extern __shared__ float S[];
    const int tid  = threadIdx.x;
    const int wid  = tid >> 5;
    const int lane = tid & 31;
    const int gq   = lane >> 2;     // group 0..7
    const int tig  = lane & 3;      // thread-in-group
    const int warp_m = wid & 1;     // 0..1 (64 rows each)
    const int warp_n = wid >> 1;    // 0..3 (32 cols each)
    const int bm = blockIdx.y * 128;
    const int bn = blockIdx.x * 128;
    const uint32_t sb = smem_u32(S);

    float acc[4][4][4];
    #pragma unroll
    for (int i = 0; i < 4; i++)
        #pragma unroll
        for (int j = 0; j < 4; j++)
            #pragma unroll
            for (int r = 0; r < 4; r++) acc[i][j][r] = 0.f;

    const int nk = K / BKT;

    // ---- tile loader: 512 16B-chunks per operand, 2 per thread ----
    const int l_row = tid >> 1;             // 0..127
    const int l_q0  = (tid & 1) << 1;       // 0 or 2  (two quads each)
    const float* Arow = A + (size_t)(bm + l_row) * K + l_q0 * 4;
    const float* Brow = B + (size_t)(bn + l_row) * K + l_q0 * 4;
    const uint32_t sArow = sb + (uint32_t)(l_row * AS_STRIDE + l_q0 * 4) * 4;
    const uint32_t sBrow = sArow + TILE_FLOATS * 4;

#define LOAD_TILE(kt, stage) do {                                              \
        const uint32_t so = (uint32_t)(stage) * (STAGE_FLOATS * 4);            \
        const size_t ko = (size_t)(kt) * BKT;                                  \
        CP_ASYNC16(sArow + so,      Arow + ko);                                \
        CP_ASYNC16(sArow + so + 16, Arow + ko + 4);                            \
        CP_ASYNC16(sBrow + so,      Brow + ko);                                \
        CP_ASYNC16(sBrow + so + 16, Brow + ko + 4);                            \
    } while (0)

    // prologue: stages 0..STAGES-2
    #pragma unroll
    for (int s = 0; s < STAGES - 1; s++) { LOAD_TILE(s, s); CP_COMMIT(); }

    for (int kt = 0; kt < nk; kt++) {
        CP_WAIT1();
        __syncthreads();

        const int stage = kt % STAGES;
        const float* sA = S + stage * STAGE_FLOATS + (warp_m * 64) * AS_STRIDE;
        const float* sB = S + stage * STAGE_FLOATS + TILE_FLOATS + (warp_n * 32) * AS_STRIDE;

        #pragma unroll
        for (int ks = 0; ks < BKT; ks += 8) {
            uint32_t ahi[4][4], alo[4][4];
            #pragma unroll
            for (int i = 0; i < 4; i++) {
                const float* r0 = sA + (i * 16 + gq) * AS_STRIDE + ks + tig;
                const float* r1 = r0 + 8 * AS_STRIDE;
                split_tf32(r0[0], ahi[i][0], alo[i][0]);
                split_tf32(r1[0], ahi[i][1], alo[i][1]);
                split_tf32(r0[4], ahi[i][2], alo[i][2]);
                split_tf32(r1[4], ahi[i][3], alo[i][3]);
            }
            uint32_t bhi[4][2], blo[4][2];
            #pragma unroll
            for (int j = 0; j < 4; j++) {
                const float* r0 = sB + (j * 8 + gq) * AS_STRIDE + ks + tig;
                split_tf32(r0[0], bhi[j][0], blo[j][0]);
                split_tf32(r0[4], bhi[j][1], blo[j][1]);
            }
            #pragma unroll
            for (int i = 0; i < 4; i++)
                #pragma unroll
                for (int j = 0; j < 4; j++) {
                    mma_tf32(acc[i][j], ahi[i], bhi[j]);
                    mma_tf32(acc[i][j], ahi[i], blo[j]);
                    mma_tf32(acc[i][j], alo[i], bhi[j]);
                }
        }
        __syncthreads();

        const int nt = kt + STAGES - 1;
        if (nt < nk) LOAD_TILE(nt, nt % STAGES);
        CP_COMMIT();
    }
#undef LOAD_TILE

    // epilogue
    #pragma unroll
    for (int i = 0; i < 4; i++) {
        const int row0 = bm + warp_m * 64 + i * 16 + gq;
        #pragma unroll
        for (int j = 0; j < 4; j++) {
            const int col = bn + warp_n * 32 + j * 8 + tig * 2;
            float2 v0 = make_float2(acc[i][j][0], acc[i][j][1]);
            float2 v1 = make_float2(acc[i][j][2], acc[i][j][3]);
            if (SILU) {
                v0.x = silu_f(v0.x); v0.y = silu_f(v0.y);
                v1.x = silu_f(v1.x); v1.y = silu_f(v1.y);
            }
            *(float2*)&C[(size_t)row0 * N + col]       = v0;
            *(float2*)&C[(size_t)(row0 + 8) * N + col] = v1;
        }
    }
}

// ---------------------------------------------------------------
// small-weight transpose: dst[c*rows + r] = src[r*cols + c]
// ---------------------------------------------------------------
__global__ void transpose_small(const float* __restrict__ src, float* __restrict__ dst,
                                int rows, int cols)
{
    int i = blockIdx.x * blockDim.x + threadIdx.x;
    if (i < rows * cols) {
        int r = i / cols, c = i % cols;
        dst[(size_t)c * rows + r] = src[i];
    }
}

// ---------------------------------------------------------------
// depthwise causal conv (K=4) + bias + SiLU.
// ---------------------------------------------------------------
__global__ void conv_silu_kernel(const float* __restrict__ conv_w,
                                 const float* __restrict__ conv_b)
{
    int idx = blockIdx.x * blockDim.x + threadIdx.x;  // over TOK*DI
    if (idx >= TOK * DI) return;
    int d = idx % DI;
    int t = idx / DI;
    int l = t % LL;
    int b = t / LL;

    float4 w = *(const float4*)&conv_w[d * KC];
    float acc = conv_b[d];
    const float* Pb = g_P + (size_t)b * LL * N2 + d;
    float wj[4] = {w.x, w.y, w.z, w.w};
    #pragma unroll
    for (int j = 0; j < KC; j++) {
        int ls = l - (KC - 1) + j;
        if (ls >= 0) acc = fmaf(wj[j], Pb[(size_t)ls * N2], acc);
    }
    g_hsc[idx] = silu_f(acc);
}

// ---------------------------------------------------------------
// x_proj: ssmp[t,k] = sum_d hsc[t,d] * xwT[d,k],  k in [0,80)
// ---------------------------------------------------------------
__global__ void xproj_kernel()
{
    __shared__ float sh[DI];
    const int t = blockIdx.x;
    for (int i = threadIdx.x; i < DI; i += blockDim.x)
        sh[i] = g_hsc[(size_t)t * DI + i];
    __syncthreads();
    const int k = threadIdx.x;
    if (k < 80) {
        float acc = 0.f;
        #pragma unroll 8
        for (int d = 0; d < DI; d++)
            acc = fmaf(sh[d], g_xwT[d * 80 + k], acc);
        g_ssmp[(size_t)t * 80 + k] = acc;
    }
}

// ---------------------------------------------------------------
// dt: dt[t,d] = softplus( ts[t,:] @ dt_w[d,:] + dt_b[d] )
// ---------------------------------------------------------------
__global__ void dt_kernel(const float* __restrict__ dt_b)
{
    __shared__ float ts[RR];
    const int t = blockIdx.x;
    if (threadIdx.x < RR) ts[threadIdx.x] = g_ssmp[(size_t)t * 80 + threadIdx.x];
    __syncthreads();
    for (int d = threadIdx.x; d < DI; d += blockDim.x) {
        float acc = dt_b[d];
        #pragma unroll
        for (int r = 0; r < RR; r++)
            acc = fmaf(ts[r], g_dtwT[r * DI + d], acc);
        float sp = (acc > 20.f) ? acc : log1pf(expf(acc));
        g_dt[(size_t)t * DI + d] = sp;
    }
}

// ---------------------------------------------------------------
// selective scan. thread per (b,d), 16-state in registers.
// ---------------------------------------------------------------
__global__ void scan_kernel(const float* __restrict__ A_log,
                            const float* __restrict__ Dp)
{
    const int d = blockIdx.x * blockDim.x + threadIdx.x;
    const int b = blockIdx.y;
    if (d >= DI) return;

    float Arow[NN];
    #pragma unroll
    for (int n = 0; n < NN; n++) Arow[n] = -expf(A_log[d * NN + n]);
    const float Dd = Dp[d];

    float s[NN];
    #pragma unroll
    for (int n = 0; n < NN; n++) s[n] = 0.f;

    for (int l = 0; l < LL; l++) {
        const size_t t = (size_t)b * LL + l;
        const float dtv = g_dt[t * DI + d];
        const float u   = g_hsc[t * DI + d];
        const float gte = g_P[t * N2 + DI + d];
        const float* bc = g_ssmp + t * 80 + RR;
        const float dtu = dtv * u;
        float y = 0.f;
        #pragma unroll
        for (int n = 0; n < NN; n++) {
            const float Bn = __ldg(bc + n);
            const float Cn = __ldg(bc + NN + n);
            const float dA = __expf(dtv * Arow[n]);
            s[n] = fmaf(dA, s[n], dtu * Bn);
            y = fmaf(s[n], Cn, y);
        }
        float zz = fmaf(u, Dd, y);
        zz *= silu_f(gte);
        g_z[t * DI + d] = zz;
    }
}

// ---------------------------------------------------------------
extern "C" void kernel_launch(void* const* d_in, const int* in_sizes, int n_in,
                              void* d_out, int out_size)
{
    const float* x          = (const float*)d_in[0];
    const float* in_up_w    = (const float*)d_in[1];
    const float* in_down_w  = (const float*)d_in[2];
    const float* conv_w     = (const float*)d_in[3];
    const float* conv_b     = (const float*)d_in[4];
    const float* x_proj_w   = (const float*)d_in[5];
    const float* dt_w       = (const float*)d_in[6];
    const float* dt_b       = (const float*)d_in[7];
    const float* A_log      = (const float*)d_in[8];
    const float* Dp         = (const float*)d_in[9];
    const float* out_up_w   = (const float*)d_in[10];
    const float* out_down_w = (const float*)d_in[11];
    float* out = (float*)d_out;

    float *t1, *P, *z, *xwT, *dtwT;
    cudaGetSymbolAddress((void**)&t1, g_t1);
    cudaGetSymbolAddress((void**)&P,  g_P);
    cudaGetSymbolAddress((void**)&z,  g_z);
    cudaGetSymbolAddress((void**)&xwT,  g_xwT);
    cudaGetSymbolAddress((void**)&dtwT, g_dtwT);

    static int attr_done = 0;
    if (!attr_done) {
        cudaFuncSetAttribute(gemm_tf32_mma<true >,
                             cudaFuncAttributeMaxDynamicSharedMemorySize, GSMEM_BYTES);
        cudaFuncSetAttribute(gemm_tf32_mma<false>,
                             cudaFuncAttributeMaxDynamicSharedMemorySize, GSMEM_BYTES);
        attr_done = 1;
    }

    // independent small transposes first
    transpose_small<<<(80*DI + 255)/256, 256>>>(x_proj_w, xwT, 80, DI);
    transpose_small<<<(DI*RR + 255)/256, 256>>>(dt_w, dtwT, DI, RR);

    // 1) up-proj + SiLU : [TOK,HH] x [N1,HH]^T -> [TOK,N1]
    gemm_tf32_mma<true ><<<dim3(N1/128, TOK/128), 256, GSMEM_BYTES>>>(x, in_up_w, t1, TOK, N1, HH);
    // 2) down-proj : [TOK,N1] x [N2,N1]^T -> [TOK,N2]  (hs | gate)
    gemm_tf32_mma<false><<<dim3(N2/128, TOK/128), 256, GSMEM_BYTES>>>(t1, in_down_w, P, TOK, N2, N1);
    // 3) depthwise causal conv + SiLU -> hsc (token-major)
    conv_silu_kernel<<<(TOK*DI + 255)/256, 256>>>(conv_w, conv_b);
    // 4) x_proj -> [TOK,80]
    xproj_kernel<<<TOK, 96>>>();
    // 5) dt = softplus(ts @ dt_w^T + dt_b)
    dt_kernel<<<TOK, 256>>>(dt_b);
    // 6) selective scan + D skip + gate -> z
    scan_kernel<<<dim3(DI/128, BB), 128>>>(A_log, Dp);
    // 7) out up-proj + SiLU : [TOK,DI] x [N3,DI]^T -> [TOK,N3]
    gemm_tf32_mma<true ><<<dim3(N3/128, TOK/128), 256, GSMEM_BYTES>>>(z, out_up_w, t1, TOK, N3, DI);
    // 8) out down-proj : [TOK,N3] x [HH,N3]^T -> [TOK,HH]
    gemm_tf32_mma<false><<<dim3(HH/128, TOK/128), 256, GSMEM_BYTES>>>(t1, out_down_w, out, TOK, HH, N3);
}

// round 5
// speedup vs baseline: 1.3008x; 1.0486x over previous
#include <cuda_runtime.h>
#include <math.h>
#include <stdint.h>

// ---------------- problem constants ----------------
#define BB 2
#define LL 1024
#define HH 768
#define DI 1536
#define NN 16
#define KC 4          // conv kernel width
#define RR 48
#define TOK (BB*LL)   // 2048 tokens
#define N1 (2*DI*4)   // 12288
#define N2 (2*DI)     // 3072
#define N3 (4*DI)     // 6144

// ---------------- device scratch (no allocs allowed) ----------------
__device__ float g_t1  [(size_t)TOK * N1];   // up-proj act, reused later
__device__ float g_P   [(size_t)TOK * N2];   // proj: cols [0,DI)=hs, [DI,2DI)=gate
__device__ float g_hsc [(size_t)TOK * DI];   // conv+silu output, token-major
__device__ float g_ssmp[(size_t)TOK * 80];   // x_proj output (R + 2N = 80)
__device__ float g_dt  [(size_t)TOK * DI];   // softplus(dt), token-major
__device__ float g_z   [(size_t)TOK * DI];   // scan output * gate, token-major
__device__ float g_dtwT[RR * DI];            // dt_w transposed [R][DI]
__device__ float g_xwT [DI * 80];            // x_proj_w transposed [DI][80]

__device__ __forceinline__ float silu_f(float x) {
    return x / (1.f + __expf(-x));
}

// ===================== mma.sync tf32 helpers =====================
__device__ __forceinline__ uint32_t smem_u32(const void* p) {
    uint32_t a;
    asm("{ .reg .u64 t; cvta.to.shared.u64 t, %1; cvt.u32.u64 %0, t; }"
        : "=r"(a) : "l"(p));
    return a;
}

#define CP_ASYNC16(dst, src) \
    asm volatile("cp.async.cg.shared.global [%0], [%1], 16;" \
                 :: "r"(dst), "l"(src) : "memory")
#define CP_COMMIT() asm volatile("cp.async.commit_group;" ::: "memory")
#define CP_WAIT1()  asm volatile("cp.async.wait_group 1;" ::: "memory")

__device__ __forceinline__ void split_tf32(float x, uint32_t& hi, uint32_t& lo) {
    uint32_t h;
    asm("cvt.rna.tf32.f32 %0, %1;" : "=r"(h) : "f"(x));
    hi = h;
    lo = __float_as_uint(x - __uint_as_float(h));
}

__device__ __forceinline__ void mma_tf32(float* c, const uint32_t* a, const uint32_t* b) {
    asm volatile("mma.sync.aligned.m16n8k8.row.col.f32.tf32.tf32.f32 "
                 "{%0,%1,%2,%3}, {%4,%5,%6,%7}, {%8,%9}, {%0,%1,%2,%3};"
                 : "+f"(c[0]), "+f"(c[1]), "+f"(c[2]), "+f"(c[3])
                 : "r"(a[0]), "r"(a[1]), "r"(a[2]), "r"(a[3]),
                   "r"(b[0]), "r"(b[1]));
}

// =====================================================================
// GEMM NT via mma.sync tf32x3:
//   C[M,N] = A[M,K] (row-major) * B[N,K] (row-major)^T
// 128x64x16 tiles, 128 threads (2x2 warps, 64x32 per warp),
// 3-stage cp.async pipeline, fp32 in smem (stride 20 pad), split in regs.
// 4 CTAs/SM resident (regs+smem sized for it) -> 16 warps/SM.
// Requires M%128==0, N%64==0, K%16==0.
// =====================================================================
#define BKT 16
#define STAGES 3
#define AS_STRIDE 20                        // floats per smem row (pad 16 -> 20)
#define A_FLOATS (128 * AS_STRIDE)          // 2560
#define B_FLOATS (64 * AS_STRIDE)           // 1280
#define STAGE_FLOATS (A_FLOATS + B_FLOATS)  // 3840
#define GSMEM_BYTES (STAGES * STAGE_FLOATS * 4)   // 46080

template<bool SILU>
__global__ __launch_bounds__(128, 4)
void gemm_tf32_mma(const float* __restrict__ A, const float* __restrict__ B,
                   float* __restrict__ C, int M, int N, int K)
{
    extern __shared__ float S[];
    const int tid  = threadIdx.x;
    const int wid  = tid >> 5;
    const int lane = tid & 31;
    const int gq   = lane >> 2;     // group 0..7
    const int tig  = lane & 3;      // thread-in-group
    const int warp_m = wid & 1;     // 0..1 (64 rows each)
    const int warp_n = wid >> 1;    // 0..1 (32 cols each)
    const int bm = blockIdx.y * 128;
    const int bn = blockIdx.x * 64;
    const uint32_t sb = smem_u32(S);

    float acc[4][4][4];
    #pragma unroll
    for (int i = 0; i < 4; i++)
        #pragma unroll
        for (int j = 0; j < 4; j++)
            #pragma unroll
            for (int r = 0; r < 4; r++) acc[i][j][r] = 0.f;

    const int nk = K / BKT;

    // ---- tile loader ----
    // A: 512 float4 chunks, 4 per thread (rows stride 32 per chunk)
    // B: 256 float4 chunks, 2 per thread
    const int l_row = tid >> 2;           // 0..31
    const int l_c0  = (tid & 3) << 2;     // 0,4,8,12
    const float* Abase = A + (size_t)(bm + l_row) * K + l_c0;
    const float* Bbase = B + (size_t)(bn + l_row) * K + l_c0;
    const uint32_t sA0 = sb + (uint32_t)(l_row * AS_STRIDE + l_c0) * 4;
    const uint32_t sB0 = sb + (uint32_t)(A_FLOATS + l_row * AS_STRIDE + l_c0) * 4;

#define LOAD_TILE(kt, stage) do {                                              \
        const uint32_t so = (uint32_t)(stage) * (STAGE_FLOATS * 4);            \
        const size_t ko = (size_t)(kt) * BKT;                                  \
        CP_ASYNC16(sA0 + so,                        Abase + ko);               \
        CP_ASYNC16(sA0 + so + 32*AS_STRIDE*4,       Abase + ko + (size_t)32*K);\
        CP_ASYNC16(sA0 + so + 64*AS_STRIDE*4,       Abase + ko + (size_t)64*K);\
        CP_ASYNC16(sA0 + so + 96*AS_STRIDE*4,       Abase + ko + (size_t)96*K);\
        CP_ASYNC16(sB0 + so,                        Bbase + ko);               \
        CP_ASYNC16(sB0 + so + 32*AS_STRIDE*4,       Bbase + ko + (size_t)32*K);\
    } while (0)

    // prologue: stages 0..STAGES-2
    #pragma unroll
    for (int s = 0; s < STAGES - 1; s++) { LOAD_TILE(s, s); CP_COMMIT(); }

    for (int kt = 0; kt < nk; kt++) {
        CP_WAIT1();
        __syncthreads();

        const int stage = kt % STAGES;
        const float* sA = S + stage * STAGE_FLOATS + (warp_m * 64) * AS_STRIDE;
        const float* sB = S + stage * STAGE_FLOATS + A_FLOATS + (warp_n * 32) * AS_STRIDE;

        #pragma unroll
        for (int ks = 0; ks < BKT; ks += 8) {
            uint32_t ahi[4][4], alo[4][4];
            #pragma unroll
            for (int i = 0; i < 4; i++) {
                const float* r0 = sA + (i * 16 + gq) * AS_STRIDE + ks + tig;
                const float* r1 = r0 + 8 * AS_STRIDE;
                split_tf32(r0[0], ahi[i][0], alo[i][0]);
                split_tf32(r1[0], ahi[i][1], alo[i][1]);
                split_tf32(r0[4], ahi[i][2], alo[i][2]);
                split_tf32(r1[4], ahi[i][3], alo[i][3]);
            }
            uint32_t bhi[4][2], blo[4][2];
            #pragma unroll
            for (int j = 0; j < 4; j++) {
                const float* r0 = sB + (j * 8 + gq) * AS_STRIDE + ks + tig;
                split_tf32(r0[0], bhi[j][0], blo[j][0]);
                split_tf32(r0[4], bhi[j][1], blo[j][1]);
            }
            #pragma unroll
            for (int i = 0; i < 4; i++)
                #pragma unroll
                for (int j = 0; j < 4; j++) {
                    mma_tf32(acc[i][j], ahi[i], bhi[j]);
                    mma_tf32(acc[i][j], ahi[i], blo[j]);
                    mma_tf32(acc[i][j], alo[i], bhi[j]);
                }
        }
        __syncthreads();

        const int nt = kt + STAGES - 1;
        if (nt < nk) LOAD_TILE(nt, nt % STAGES);
        CP_COMMIT();
    }
#undef LOAD_TILE

    // epilogue
    #pragma unroll
    for (int i = 0; i < 4; i++) {
        const int row0 = bm + warp_m * 64 + i * 16 + gq;
        #pragma unroll
        for (int j = 0; j < 4; j++) {
            const int col = bn + warp_n * 32 + j * 8 + tig * 2;
            float2 v0 = make_float2(acc[i][j][0], acc[i][j][1]);
            float2 v1 = make_float2(acc[i][j][2], acc[i][j][3]);
            if (SILU) {
                v0.x = silu_f(v0.x); v0.y = silu_f(v0.y);
                v1.x = silu_f(v1.x); v1.y = silu_f(v1.y);
            }
            *(float2*)&C[(size_t)row0 * N + col]       = v0;
            *(float2*)&C[(size_t)(row0 + 8) * N + col] = v1;
        }
    }
}

// ---------------------------------------------------------------
// small-weight transpose: dst[c*rows + r] = src[r*cols + c]
// ---------------------------------------------------------------
__global__ void transpose_small(const float* __restrict__ src, float* __restrict__ dst,
                                int rows, int cols)
{
    int i = blockIdx.x * blockDim.x + threadIdx.x;
    if (i < rows * cols) {
        int r = i / cols, c = i % cols;
        dst[(size_t)c * rows + r] = src[i];
    }
}

// ---------------------------------------------------------------
// depthwise causal conv (K=4) + bias + SiLU.
// ---------------------------------------------------------------
__global__ void conv_silu_kernel(const float* __restrict__ conv_w,
                                 const float* __restrict__ conv_b)
{
    int idx = blockIdx.x * blockDim.x + threadIdx.x;  // over TOK*DI
    if (idx >= TOK * DI) return;
    int d = idx % DI;
    int t = idx / DI;
    int l = t % LL;
    int b = t / LL;

    float4 w = *(const float4*)&conv_w[d * KC];
    float acc = conv_b[d];
    const float* Pb = g_P + (size_t)b * LL * N2 + d;
    float wj[4] = {w.x, w.y, w.z, w.w};
    #pragma unroll
    for (int j = 0; j < KC; j++) {
        int ls = l - (KC - 1) + j;
        if (ls >= 0) acc = fmaf(wj[j], Pb[(size_t)ls * N2], acc);
    }
    g_hsc[idx] = silu_f(acc);
}

// ---------------------------------------------------------------
// x_proj: ssmp[t,k] = sum_d hsc[t,d] * xwT[d,k],  k in [0,80)
// ---------------------------------------------------------------
__global__ void xproj_kernel()
{
    __shared__ float sh[DI];
    const int t = blockIdx.x;
    for (int i = threadIdx.x; i < DI; i += blockDim.x)
        sh[i] = g_hsc[(size_t)t * DI + i];
    __syncthreads();
    const int k = threadIdx.x;
    if (k < 80) {
        float acc = 0.f;
        #pragma unroll 8
        for (int d = 0; d < DI; d++)
            acc = fmaf(sh[d], g_xwT[d * 80 + k], acc);
        g_ssmp[(size_t)t * 80 + k] = acc;
    }
}

// ---------------------------------------------------------------
// dt: dt[t,d] = softplus( ts[t,:] @ dt_w[d,:] + dt_b[d] )
// ---------------------------------------------------------------
__global__ void dt_kernel(const float* __restrict__ dt_b)
{
    __shared__ float ts[RR];
    const int t = blockIdx.x;
    if (threadIdx.x < RR) ts[threadIdx.x] = g_ssmp[(size_t)t * 80 + threadIdx.x];
    __syncthreads();
    for (int d = threadIdx.x; d < DI; d += blockDim.x) {
        float acc = dt_b[d];
        #pragma unroll
        for (int r = 0; r < RR; r++)
            acc = fmaf(ts[r], g_dtwT[r * DI + d], acc);
        float sp = (acc > 20.f) ? acc : log1pf(expf(acc));
        g_dt[(size_t)t * DI + d] = sp;
    }
}

// ---------------------------------------------------------------
// selective scan. thread per (b,d), 16-state in registers.
// ---------------------------------------------------------------
__global__ void scan_kernel(const float* __restrict__ A_log,
                            const float* __restrict__ Dp)
{
    const int d = blockIdx.x * blockDim.x + threadIdx.x;
    const int b = blockIdx.y;
    if (d >= DI) return;

    float Arow[NN];
    #pragma unroll
    for (int n = 0; n < NN; n++) Arow[n] = -expf(A_log[d * NN + n]);
    const float Dd = Dp[d];

    float s[NN];
    #pragma unroll
    for (int n = 0; n < NN; n++) s[n] = 0.f;

    for (int l = 0; l < LL; l++) {
        const size_t t = (size_t)b * LL + l;
        const float dtv = g_dt[t * DI + d];
        const float u   = g_hsc[t * DI + d];
        const float gte = g_P[t * N2 + DI + d];
        const float* bc = g_ssmp + t * 80 + RR;
        const float dtu = dtv * u;
        float y = 0.f;
        #pragma unroll
        for (int n = 0; n < NN; n++) {
            const float Bn = __ldg(bc + n);
            const float Cn = __ldg(bc + NN + n);
            const float dA = __expf(dtv * Arow[n]);
            s[n] = fmaf(dA, s[n], dtu * Bn);
            y = fmaf(s[n], Cn, y);
        }
        float zz = fmaf(u, Dd, y);
        zz *= silu_f(gte);
        g_z[t * DI + d] = zz;
    }
}

// ---------------------------------------------------------------
extern "C" void kernel_launch(void* const* d_in, const int* in_sizes, int n_in,
                              void* d_out, int out_size)
{
    const float* x          = (const float*)d_in[0];
    const float* in_up_w    = (const float*)d_in[1];
    const float* in_down_w  = (const float*)d_in[2];
    const float* conv_w     = (const float*)d_in[3];
    const float* conv_b     = (const float*)d_in[4];
    const float* x_proj_w   = (const float*)d_in[5];
    const float* dt_w       = (const float*)d_in[6];
    const float* dt_b       = (const float*)d_in[7];
    const float* A_log      = (const float*)d_in[8];
    const float* Dp         = (const float*)d_in[9];
    const float* out_up_w   = (const float*)d_in[10];
    const float* out_down_w = (const float*)d_in[11];
    float* out = (float*)d_out;

    float *t1, *P, *z, *xwT, *dtwT;
    cudaGetSymbolAddress((void**)&t1, g_t1);
    cudaGetSymbolAddress((void**)&P,  g_P);
    cudaGetSymbolAddress((void**)&z,  g_z);
    cudaGetSymbolAddress((void**)&xwT,  g_xwT);
    cudaGetSymbolAddress((void**)&dtwT, g_dtwT);

    static int attr_done = 0;
    if (!attr_done) {
        cudaFuncSetAttribute(gemm_tf32_mma<true >,
                             cudaFuncAttributeMaxDynamicSharedMemorySize, GSMEM_BYTES);
        cudaFuncSetAttribute(gemm_tf32_mma<false>,
                             cudaFuncAttributeMaxDynamicSharedMemorySize, GSMEM_BYTES);
        attr_done = 1;
    }

    // independent small transposes first
    transpose_small<<<(80*DI + 255)/256, 256>>>(x_proj_w, xwT, 80, DI);
    transpose_small<<<(DI*RR + 255)/256, 256>>>(dt_w, dtwT, DI, RR);

    // 1) up-proj + SiLU : [TOK,HH] x [N1,HH]^T -> [TOK,N1]
    gemm_tf32_mma<true ><<<dim3(N1/64, TOK/128), 128, GSMEM_BYTES>>>(x, in_up_w, t1, TOK, N1, HH);
    // 2) down-proj : [TOK,N1] x [N2,N1]^T -> [TOK,N2]  (hs | gate)
    gemm_tf32_mma<false><<<dim3(N2/64, TOK/128), 128, GSMEM_BYTES>>>(t1, in_down_w, P, TOK, N2, N1);
    // 3) depthwise causal conv + SiLU -> hsc (token-major)
    conv_silu_kernel<<<(TOK*DI + 255)/256, 256>>>(conv_w, conv_b);
    // 4) x_proj -> [TOK,80]
    xproj_kernel<<<TOK, 96>>>();
    // 5) dt = softplus(ts @ dt_w^T + dt_b)
    dt_kernel<<<TOK, 256>>>(dt_b);
    // 6) selective scan + D skip + gate -> z
    scan_kernel<<<dim3(DI/128, BB), 128>>>(A_log, Dp);
    // 7) out up-proj + SiLU : [TOK,DI] x [N3,DI]^T -> [TOK,N3]
    gemm_tf32_mma<true ><<<dim3(N3/64, TOK/128), 128, GSMEM_BYTES>>>(z, out_up_w, t1, TOK, N3, DI);
    // 8) out down-proj : [TOK,N3] x [HH,N3]^T -> [TOK,HH]
    gemm_tf32_mma<false><<<dim3(HH/64, TOK/128), 128, GSMEM_BYTES>>>(t1, out_down_w, out, TOK, HH, N3);
}